// round 12
// baseline (speedup 1.0000x reference)
#include <cuda_runtime.h>

#define IMG_H 512
#define IMG_W 512
#define RAD   5
#define KS    11

#define H_T 8
#define SSTRIDE 522
#define NTHREADS 512
#define NBLOCKS ((IMG_H / H_T) * 96)   // 64 * 96 = 6144

#define G0d 1.0
#define G1d 0.8007374029168081
#define G2d 0.4111122905071874
#define G3d 0.1353352832366127
#define G4d 0.0285655007845504
#define G5d 0.0038659201394728
#define GSd (G0d + 2.0*(G1d+G2d+G3d+G4d+G5d))

__device__ constexpr float WK[11] = {
    (float)(G5d/GSd), (float)(G4d/GSd), (float)(G3d/GSd), (float)(G2d/GSd), (float)(G1d/GSd),
    (float)(G0d/GSd),
    (float)(G1d/GSd), (float)(G2d/GSd), (float)(G3d/GSd), (float)(G4d/GSd), (float)(G5d/GSd)
};

#define C1F 0.0001f
#define C2F 0.0009f

#define SMEM_BYTES (5 * H_T * SSTRIDE * 4)   // 83,520 -> 2 blocks/SM

typedef unsigned long long u64;

__device__ __forceinline__ u64 pack2(float x, float y) {
    u64 r; asm("mov.b64 %0, {%1, %2};" : "=l"(r) : "f"(x), "f"(y)); return r;
}
__device__ __forceinline__ void unpack2(u64 v, float& x, float& y) {
    asm("mov.b64 {%0, %1}, %2;" : "=f"(x), "=f"(y) : "l"(v));
}
__device__ __forceinline__ void fma2(u64& d, u64 a, u64 b) {
    asm("fma.rn.f32x2 %0, %1, %2, %0;" : "+l"(d) : "l"(a), "l"(b));
}
__device__ __forceinline__ u64 mul2(u64 a, u64 b) {
    u64 r; asm("mul.rn.f32x2 %0, %1, %2;" : "=l"(r) : "l"(a), "l"(b)); return r;
}

__device__ double   g_ssim_sum;   // zero at load; last block restores 0 each run
__device__ unsigned g_done;       // zero at load; last block restores 0 each run

// Vertical blur, ONE 4-row chunk per call: 14 input rows -> 4 output rows.
template<bool INTERIOR>
__device__ __forceinline__ void v_chunk(
    const float* __restrict__ p, const float* __restrict__ t,
    float* __restrict__ sV, int ty0, int col, int chunk)
{
    const int gy0 = ty0 + chunk * 4 - RAD;

    u64   acc01[4], acc23[4];
    float acc4[4];
    #pragma unroll
    for (int o = 0; o < 4; o++) { acc01[o] = 0ull; acc23[o] = 0ull; acc4[o] = 0.0f; }

    const float* pp = p + (long)gy0 * IMG_W + col;
    const float* tt = t + (long)gy0 * IMG_W + col;

    #pragma unroll
    for (int i = 0; i < 14; i++) {
        float pv, tv;
        if (INTERIOR) {
            pv = pp[i * IMG_W];
            tv = tt[i * IMG_W];
        } else {
            const bool ok = ((unsigned)(gy0 + i) < (unsigned)IMG_H);
            pv = ok ? pp[i * IMG_W] : 0.0f;
            tv = ok ? tt[i * IMG_W] : 0.0f;
        }
        const u64   a01 = pack2(pv, tv);
        const u64   a23 = mul2(a01, a01);        // (p*p, t*t)
        const float a4  = pv * tv;
        #pragma unroll
        for (int o = 0; o < 4; o++) {
            const int k = i - o;
            if (k >= 0 && k < KS) {              // compile-time pruned
                const int kk = (k < 6) ? k : (10 - k);
                const u64 ww = pack2(WK[kk], WK[kk]);
                fma2(acc01[o], a01, ww);
                fma2(acc23[o], a23, ww);
                acc4[o] = fmaf(a4, WK[kk], acc4[o]);
            }
        }
    }

    float* base = sV + col + RAD;
    #pragma unroll
    for (int o = 0; o < 4; o++) {
        const int r = chunk * 4 + o;
        float x0, x1, x2, x3;
        unpack2(acc01[o], x0, x1);
        unpack2(acc23[o], x2, x3);
        base[(0 * H_T + r) * SSTRIDE] = x0;
        base[(1 * H_T + r) * SSTRIDE] = x1;
        base[(2 * H_T + r) * SSTRIDE] = x2;
        base[(3 * H_T + r) * SSTRIDE] = x3;
        base[(4 * H_T + r) * SSTRIDE] = acc4[o];
    }
}

__global__ __launch_bounds__(NTHREADS, 2) void ssim_tile_kernel(
    const float* __restrict__ pred,
    const float* __restrict__ target,
    float* __restrict__ out, double invN)
{
    extern __shared__ float sV[];            // [5][H_T][SSTRIDE]
    __shared__ float red[NTHREADS / 32];

    const int ty0 = blockIdx.x * H_T;
    const size_t img_off = (size_t)blockIdx.y * (IMG_H * IMG_W);
    const float* __restrict__ p = pred + img_off;
    const float* __restrict__ t = target + img_off;

    // ---- zero the 10 halo columns: 5 fields * 8 rows * 10 cols = 400 ----
    if (threadIdx.x < 400) {
        const int z = threadIdx.x;
        const int cz = z % 10;
        const int rz = (z / 10) % H_T;
        const int fz = z / (10 * H_T);
        const int j = (cz < 5) ? cz : (SSTRIDE - 10 + cz);
        sV[(fz * H_T + rz) * SSTRIDE + j] = 0.0f;
    }

    // ---- Phase V: 2 chunk-tasks per thread ----
    const bool interior = (blockIdx.x > 0) && (blockIdx.x < gridDim.x - 1);
    if (interior) {
        v_chunk<true >(p, t, sV, ty0, threadIdx.x, 0);
        v_chunk<true >(p, t, sV, ty0, threadIdx.x, 1);
    } else {
        v_chunk<false>(p, t, sV, ty0, threadIdx.x, 0);
        v_chunk<false>(p, t, sV, ty0, threadIdx.x, 1);
    }
    __syncthreads();

    // ---- Phase H: packed horizontal blur + SSIM (one task/thread) ----
    float ssum = 0.0f;
    {
        const int tid = threadIdx.x;
        const int r  = tid & 7;
        const int b3 = (tid >> 3) & 1;
        const int b4 = (tid >> 4) & 1;
        const int chunk = (tid >> 5) * 4 + 2 * b3 + b4;   // conflict-free remap
        const int c0 = chunk * 8;

        const float* hb = sV + r * SSTRIDE + c0;

        u64   m01[8], m23[8];
        float m4[8];
        #pragma unroll
        for (int o = 0; o < 8; o++) { m01[o] = 0ull; m23[o] = 0ull; m4[o] = 0.0f; }

        #pragma unroll
        for (int i2 = 0; i2 < 9; i2++) {
            const float2 v0 = *(const float2*)(hb + 0 * H_T * SSTRIDE + 2 * i2);
            const float2 v1 = *(const float2*)(hb + 1 * H_T * SSTRIDE + 2 * i2);
            const float2 v2 = *(const float2*)(hb + 2 * H_T * SSTRIDE + 2 * i2);
            const float2 v3 = *(const float2*)(hb + 3 * H_T * SSTRIDE + 2 * i2);
            const float2 v4 = *(const float2*)(hb + 4 * H_T * SSTRIDE + 2 * i2);
            #pragma unroll
            for (int half = 0; half < 2; half++) {
                const int i = 2 * i2 + half;
                const float a0 = half ? v0.y : v0.x;
                const float a1 = half ? v1.y : v1.x;
                const float a2 = half ? v2.y : v2.x;
                const float a3 = half ? v3.y : v3.x;
                const float a4 = half ? v4.y : v4.x;
                const u64 a01 = pack2(a0, a1);
                const u64 a23 = pack2(a2, a3);
                #pragma unroll
                for (int o = 0; o < 8; o++) {
                    const int k = i - o;
                    if (k >= 0 && k < KS) {
                        const int kk = (k < 6) ? k : (10 - k);
                        const u64 ww = pack2(WK[kk], WK[kk]);
                        fma2(m01[o], a01, ww);
                        fma2(m23[o], a23, ww);
                        m4[o] = fmaf(a4, WK[kk], m4[o]);
                    }
                }
            }
        }

        #pragma unroll
        for (int o = 0; o < 8; o++) {
            float mu_p, mu_t, bp2, bt2;
            unpack2(m01[o], mu_p, mu_t);
            unpack2(m23[o], bp2, bt2);
            const float mu_p2 = mu_p * mu_p;
            const float mu_t2 = mu_t * mu_t;
            const float mu_pt = mu_p * mu_t;
            const float sig_p  = bp2 - mu_p2;
            const float sig_t  = bt2 - mu_t2;
            const float sig_pt = m4[o] - mu_pt;
            const float num = (2.0f * mu_pt + C1F) * (2.0f * sig_pt + C2F);
            const float den = (mu_p2 + mu_t2 + C1F) * (sig_p + sig_t + C2F);
            ssum += __fdividef(num, den);
        }
    }

    // ---- block reduction -> one double atomicAdd + fused finalize ----
    #pragma unroll
    for (int o = 16; o > 0; o >>= 1)
        ssum += __shfl_down_sync(0xFFFFFFFFu, ssum, o);
    if ((threadIdx.x & 31) == 0)
        red[threadIdx.x >> 5] = ssum;
    __syncthreads();
    if (threadIdx.x < NTHREADS / 32) {
        float v = red[threadIdx.x];
        #pragma unroll
        for (int o = (NTHREADS / 64); o > 0; o >>= 1)
            v += __shfl_down_sync(0xFFFFFFFFu, v, o);
        if (threadIdx.x == 0) {
            atomicAdd(&g_ssim_sum, (double)v);
            __threadfence();
            const unsigned ticket = atomicAdd(&g_done, 1u);
            if (ticket == (unsigned)(NBLOCKS - 1)) {
                // All other blocks' sum-atomics are visible (fence before ticket).
                const double s = *((volatile double*)&g_ssim_sum);
                out[0] = (float)(1.0 - s * invN);
                *((volatile double*)&g_ssim_sum) = 0.0;    // restore invariant
                *((volatile unsigned*)&g_done)   = 0u;
                __threadfence();
            }
        }
    }
}

extern "C" void kernel_launch(void* const* d_in, const int* in_sizes, int n_in,
                              void* d_out, int out_size)
{
    const float* pred   = (const float*)d_in[0];
    const float* target = (const float*)d_in[1];
    float* out = (float*)d_out;

    const long long n = in_sizes[0];                 // 32*3*512*512
    const int imgs = (int)(n / (IMG_H * IMG_W));     // 96 planes

    cudaFuncSetAttribute(ssim_tile_kernel,
                         cudaFuncAttributeMaxDynamicSharedMemorySize, SMEM_BYTES);

    dim3 grid(IMG_H / H_T, imgs);                    // (64, 96) = 6144 blocks
    ssim_tile_kernel<<<grid, NTHREADS, SMEM_BYTES>>>(pred, target, out,
                                                     1.0 / (double)n);
}

// round 13
// speedup vs baseline: 1.1896x; 1.1896x over previous
#include <cuda_runtime.h>

#define IMG_H 512
#define IMG_W 512
#define RAD   5
#define KS    11

#define H_T 8
#define SCOLS 523              // 522 used + 1 pad; odd float2 stride -> conflict-free
#define NTHREADS 512

#define G0d 1.0
#define G1d 0.8007374029168081
#define G2d 0.4111122905071874
#define G3d 0.1353352832366127
#define G4d 0.0285655007845504
#define G5d 0.0038659201394728
#define GSd (G0d + 2.0*(G1d+G2d+G3d+G4d+G5d))

__device__ constexpr float WK[11] = {
    (float)(G5d/GSd), (float)(G4d/GSd), (float)(G3d/GSd), (float)(G2d/GSd), (float)(G1d/GSd),
    (float)(G0d/GSd),
    (float)(G1d/GSd), (float)(G2d/GSd), (float)(G3d/GSd), (float)(G4d/GSd), (float)(G5d/GSd)
};

#define C1F 0.0001f
#define C2F 0.0009f

// smem layout: s01 float2[H_T][SCOLS], s23 float2[H_T][SCOLS], s4 float[H_T][SCOLS]
#define S01_OFF 0
#define S23_OFF (H_T * SCOLS * 8)                    // 33472
#define S4_OFF  (2 * H_T * SCOLS * 8)                // 66944
#define SMEM_BYTES (S4_OFF + H_T * SCOLS * 4)        // 83,680 -> 2 blocks/SM

typedef unsigned long long u64;

__device__ __forceinline__ u64 pack2(float x, float y) {
    u64 r; asm("mov.b64 %0, {%1, %2};" : "=l"(r) : "f"(x), "f"(y)); return r;
}
__device__ __forceinline__ void unpack2(u64 v, float& x, float& y) {
    asm("mov.b64 {%0, %1}, %2;" : "=f"(x), "=f"(y) : "l"(v));
}
__device__ __forceinline__ void fma2(u64& d, u64 a, u64 b) {
    asm("fma.rn.f32x2 %0, %1, %2, %0;" : "+l"(d) : "l"(a), "l"(b));
}
__device__ __forceinline__ u64 mul2(u64 a, u64 b) {
    u64 r; asm("mul.rn.f32x2 %0, %1, %2;" : "=l"(r) : "l"(a), "l"(b)); return r;
}

__device__ double g_ssim_sum;   // zero at load; finalize restores 0 each run

__global__ void finalize_kernel(float* out, double invN) {
    out[0] = (float)(1.0 - g_ssim_sum * invN);
    g_ssim_sum = 0.0;
}

// Vertical blur, one 4-row chunk: 14 input rows -> 4 output rows, packed stores.
template<bool INTERIOR>
__device__ __forceinline__ void v_chunk(
    const float* __restrict__ p, const float* __restrict__ t,
    char* __restrict__ smem, int ty0, int col, int chunk)
{
    const int gy0 = ty0 + chunk * 4 - RAD;

    u64   acc01[4], acc23[4];
    float acc4[4];
    #pragma unroll
    for (int o = 0; o < 4; o++) { acc01[o] = 0ull; acc23[o] = 0ull; acc4[o] = 0.0f; }

    const float* pp = p + (long)gy0 * IMG_W + col;
    const float* tt = t + (long)gy0 * IMG_W + col;

    #pragma unroll
    for (int i = 0; i < 14; i++) {
        float pv, tv;
        if (INTERIOR) {
            pv = pp[i * IMG_W];
            tv = tt[i * IMG_W];
        } else {
            const bool ok = ((unsigned)(gy0 + i) < (unsigned)IMG_H);
            pv = ok ? pp[i * IMG_W] : 0.0f;
            tv = ok ? tt[i * IMG_W] : 0.0f;
        }
        const u64   a01 = pack2(pv, tv);
        const u64   a23 = mul2(a01, a01);        // (p*p, t*t)
        const float a4  = pv * tv;
        #pragma unroll
        for (int o = 0; o < 4; o++) {
            const int k = i - o;
            if (k >= 0 && k < KS) {              // compile-time pruned
                const int kk = (k < 6) ? k : (10 - k);
                const u64 ww = pack2(WK[kk], WK[kk]);
                fma2(acc01[o], a01, ww);
                fma2(acc23[o], a23, ww);
                acc4[o] = fmaf(a4, WK[kk], acc4[o]);
            }
        }
    }

    const int j = col + RAD;                     // smem column
    u64*   s01 = (u64*)(smem + S01_OFF);
    u64*   s23 = (u64*)(smem + S23_OFF);
    float* s4  = (float*)(smem + S4_OFF);
    #pragma unroll
    for (int o = 0; o < 4; o++) {
        const int r = chunk * 4 + o;
        s01[r * SCOLS + j] = acc01[o];           // STS.64, no unpack
        s23[r * SCOLS + j] = acc23[o];           // STS.64
        s4 [r * SCOLS + j] = acc4[o];            // STS.32
    }
}

__global__ __launch_bounds__(NTHREADS, 2) void ssim_tile_kernel(
    const float* __restrict__ pred,
    const float* __restrict__ target)
{
    extern __shared__ char smem[];
    __shared__ float red[NTHREADS / 32];

    const int ty0 = blockIdx.x * H_T;
    const size_t img_off = (size_t)blockIdx.y * (IMG_H * IMG_W);
    const float* __restrict__ p = pred + img_off;
    const float* __restrict__ t = target + img_off;

    // ---- zero the 10 halo columns: 8 rows * 10 cols, all 3 arrays ----
    if (threadIdx.x < 80) {
        const int z  = threadIdx.x;
        const int cz = z % 10;
        const int rz = z / 10;
        const int j  = (cz < 5) ? cz : (512 + cz);       // 0-4 or 517-521
        ((u64*)(smem + S01_OFF))[rz * SCOLS + j] = 0ull;
        ((u64*)(smem + S23_OFF))[rz * SCOLS + j] = 0ull;
        ((float*)(smem + S4_OFF))[rz * SCOLS + j] = 0.0f;
    }

    // ---- Phase V: 2 chunk-tasks per thread ----
    const bool interior = (blockIdx.x > 0) && (blockIdx.x < gridDim.x - 1);
    if (interior) {
        v_chunk<true >(p, t, smem, ty0, threadIdx.x, 0);
        v_chunk<true >(p, t, smem, ty0, threadIdx.x, 1);
    } else {
        v_chunk<false>(p, t, smem, ty0, threadIdx.x, 0);
        v_chunk<false>(p, t, smem, ty0, threadIdx.x, 1);
    }
    __syncthreads();

    // ---- Phase H: packed horizontal blur + SSIM (one task/thread) ----
    float ssum = 0.0f;
    {
        const int tid = threadIdx.x;
        const int r  = tid & 7;
        const int b3 = (tid >> 3) & 1;
        const int b4 = (tid >> 4) & 1;
        const int chunk = (tid >> 5) * 4 + b3 + 2 * b4;  // conflict-free remap
        const int c0 = chunk * 8;

        const u64*   b01 = (const u64*)(smem + S01_OFF) + r * SCOLS + c0;
        const u64*   b23 = (const u64*)(smem + S23_OFF) + r * SCOLS + c0;
        const float* b4p = (const float*)(smem + S4_OFF) + r * SCOLS + c0;

        u64   m01[8], m23[8];
        float m4[8];
        #pragma unroll
        for (int o = 0; o < 8; o++) { m01[o] = 0ull; m23[o] = 0ull; m4[o] = 0.0f; }

        #pragma unroll
        for (int i = 0; i < 18; i++) {
            const u64   a01 = b01[i];            // LDS.64, pre-packed (p,t)
            const u64   a23 = b23[i];            // LDS.64, pre-packed (p2,t2)
            const float a4  = b4p[i];            // LDS.32
            #pragma unroll
            for (int o = 0; o < 8; o++) {
                const int k = i - o;
                if (k >= 0 && k < KS) {          // compile-time pruned
                    const int kk = (k < 6) ? k : (10 - k);
                    const u64 ww = pack2(WK[kk], WK[kk]);
                    fma2(m01[o], a01, ww);
                    fma2(m23[o], a23, ww);
                    m4[o] = fmaf(a4, WK[kk], m4[o]);
                }
            }
        }

        #pragma unroll
        for (int o = 0; o < 8; o++) {
            float mu_p, mu_t, bp2, bt2;
            unpack2(m01[o], mu_p, mu_t);
            unpack2(m23[o], bp2, bt2);
            const float mu_p2 = mu_p * mu_p;
            const float mu_t2 = mu_t * mu_t;
            const float mu_pt = mu_p * mu_t;
            const float sig_p  = bp2 - mu_p2;
            const float sig_t  = bt2 - mu_t2;
            const float sig_pt = m4[o] - mu_pt;
            const float num = (2.0f * mu_pt + C1F) * (2.0f * sig_pt + C2F);
            const float den = (mu_p2 + mu_t2 + C1F) * (sig_p + sig_t + C2F);
            ssum += __fdividef(num, den);
        }
    }

    // ---- block reduction -> one double atomicAdd ----
    #pragma unroll
    for (int o = 16; o > 0; o >>= 1)
        ssum += __shfl_down_sync(0xFFFFFFFFu, ssum, o);
    if ((threadIdx.x & 31) == 0)
        red[threadIdx.x >> 5] = ssum;
    __syncthreads();
    if (threadIdx.x < NTHREADS / 32) {
        float v = red[threadIdx.x];
        #pragma unroll
        for (int o = (NTHREADS / 64); o > 0; o >>= 1)
            v += __shfl_down_sync(0xFFFFFFFFu, v, o);
        if (threadIdx.x == 0)
            atomicAdd(&g_ssim_sum, (double)v);
    }
}

extern "C" void kernel_launch(void* const* d_in, const int* in_sizes, int n_in,
                              void* d_out, int out_size)
{
    const float* pred   = (const float*)d_in[0];
    const float* target = (const float*)d_in[1];
    float* out = (float*)d_out;

    const long long n = in_sizes[0];                 // 32*3*512*512
    const int imgs = (int)(n / (IMG_H * IMG_W));     // 96 planes

    cudaFuncSetAttribute(ssim_tile_kernel,
                         cudaFuncAttributeMaxDynamicSharedMemorySize, SMEM_BYTES);

    dim3 grid(IMG_H / H_T, imgs);                    // (64, 96)
    ssim_tile_kernel<<<grid, NTHREADS, SMEM_BYTES>>>(pred, target);

    finalize_kernel<<<1, 1>>>(out, 1.0 / (double)n);
}